// round 4
// baseline (speedup 1.0000x reference)
#include <cuda_runtime.h>
#include <cstdint>

// Leaky RNN: x_t = 0.9*x_{t-1} + 0.1*(u@Win + tanh(x_{t-1})@Wrec + brec) + q_t
//            z_t = tanh(x_t)@Wout + bout
// T=1024, B=64, NIN=32, N=256, NOUT=16.
//
// Kernel A: 64 CTAs (one per batch), 256 threads, thread owns column gn=tid.
//   Wrec[:,gn] (128 packed f32x2 regs) + Win[:,gn] (16 packed) register-stationary.
//   Per step: full-r broadcast from smem -> 144 FFMA2 -> x update -> tanh -> STS.
//   ONE __syncthreads per step. No clusters, no mbarriers, no fences.
// Kernel B: outputs = tanh(states) @ Wout + bout (DRAM-bound post-pass).

#define T_STEPS 1024
#define B_SZ    64
#define N_IN    32
#define N_HID   256
#define N_OUT   16

typedef unsigned long long ull;

__device__ __forceinline__ void ffma2(ull& acc, ull a, ull b) {
    asm("fma.rn.f32x2 %0, %1, %2, %0;" : "+l"(acc) : "l"(a), "l"(b));
}
__device__ __forceinline__ ull fadd2(ull a, ull b) {
    ull r; asm("add.rn.f32x2 %0, %1, %2;" : "=l"(r) : "l"(a), "l"(b)); return r;
}
__device__ __forceinline__ ull pack2(float lo, float hi) {
    ull r; asm("mov.b64 %0, {%1, %2};" : "=l"(r) : "f"(lo), "f"(hi)); return r;
}
__device__ __forceinline__ float hadd2(ull a) {
    float lo, hi; asm("mov.b64 {%0, %1}, %2;" : "=f"(lo), "=f"(hi) : "l"(a));
    return lo + hi;
}
__device__ __forceinline__ float ftanh(float x) {
    // tanh via exp2-based __expf: ~1e-7 rel err, robust at +/-inf
    float e = __expf(2.0f * x);
    return 1.0f - __fdividef(2.0f, e + 1.0f);
}

__global__ void __launch_bounds__(256, 1)
rnn_step_kernel(const float* __restrict__ inputs,   // [T,B,NIN]
                const float* __restrict__ noise,    // [T,B,N]
                const float* __restrict__ x0,       // [B,N]
                const float* __restrict__ Win,      // [NIN,N]
                const float* __restrict__ Wrec,     // [N,N]
                const float* __restrict__ brec,     // [N]
                float* __restrict__ states)         // [T,B,N]
{
    __shared__ __align__(16) float r_s[2][N_HID];   // r double-buffered by parity
    __shared__ __align__(16) float sU[2][N_IN];     // u_t double-buffered

    const int tid = threadIdx.x;
    const int b   = blockIdx.x;
    const int gn  = tid;

    // ---- register-stationary weights ----
    ull w[128];                                     // (Wrec[2j][gn], Wrec[2j+1][gn])
#pragma unroll
    for (int j = 0; j < 128; ++j)
        w[j] = pack2(Wrec[(2 * j) * N_HID + gn], Wrec[(2 * j + 1) * N_HID + gn]);
    ull w_in[16];                                   // (Win[2i][gn], Win[2i+1][gn])
#pragma unroll
    for (int i = 0; i < 16; ++i)
        w_in[i] = pack2(Win[(2 * i) * N_HID + gn], Win[(2 * i + 1) * N_HID + gn]);
    const float brec_r = brec[gn];

    // ---- state init ----
    float x    = x0[b * N_HID + gn];
    float qreg = noise[b * N_HID + gn];             // q_0
    float ureg = 0.0f;
    if (tid < N_IN) {
        sU[0][tid] = inputs[b * N_IN + tid];                        // u_0
        ureg       = inputs[1 * (B_SZ * N_IN) + b * N_IN + tid];    // u_1
    }
    r_s[0][gn] = ftanh(x);                          // r_{-1}
    __syncthreads();

    const float* noise_p  = noise  + b * N_HID + gn;
    float*       states_p = states + b * N_HID + gn;
    const float* inputs_p = inputs + b * N_IN;

#pragma unroll 2
    for (int t = 0; t < T_STEPS; ++t) {
        const int p  = t & 1;
        const int nb = p ^ 1;

        // prefetch q_{t+1} early (hidden under the dot)
        const int tq = (t + 1 < T_STEPS) ? (t + 1) : (T_STEPS - 1);
        const float qnext = noise_p[tq * (B_SZ * N_HID)];

        // ---- full recurrent dot: 256 MACs = 128 FFMA2, r broadcast from smem ----
        const ulonglong2* rp = reinterpret_cast<const ulonglong2*>(&r_s[p][0]);
        ull a0 = 0, a1 = 0, a2 = 0, a3 = 0;
#pragma unroll
        for (int g = 0; g < 32; ++g) {
            ulonglong2 q0 = rp[2 * g];
            ulonglong2 q1 = rp[2 * g + 1];
            ffma2(a0, w[4 * g + 0], q0.x);
            ffma2(a1, w[4 * g + 1], q0.y);
            ffma2(a2, w[4 * g + 2], q1.x);
            ffma2(a3, w[4 * g + 3], q1.y);
        }

        // ---- input projection: 32 MACs = 16 FFMA2 ----
        const ulonglong2* up = reinterpret_cast<const ulonglong2*>(&sU[p][0]);
        ull c0 = 0, c1 = 0;
#pragma unroll
        for (int g = 0; g < 8; ++g) {
            ulonglong2 u2 = up[g];
            ffma2(c0, w_in[2 * g + 0], u2.x);
            ffma2(c1, w_in[2 * g + 1], u2.y);
        }

        float tot = hadd2(fadd2(fadd2(a0, a1), fadd2(a2, a3)))
                  + hadd2(fadd2(c0, c1)) + brec_r;
        x = 0.9f * x + 0.1f * tot + qreg;
        qreg = qnext;

        states_p[t * (B_SZ * N_HID)] = x;           // fire-and-forget STG
        r_s[nb][gn] = ftanh(x);

        if (tid < N_IN) {                           // stage u_{t+1}, prefetch u_{t+2}
            sU[nb][tid] = ureg;
            const int tn = (t + 2 < T_STEPS) ? (t + 2) : (T_STEPS - 1);
            ureg = inputs_p[tn * (B_SZ * N_IN) + tid];
        }

        __syncthreads();                            // r_s[nb]/sU[nb] ready for t+1
    }
}

// ---------------- Kernel B: z = tanh(states) @ Wout + bout ----------------
// Warp per row (t,b). Wout packed register-stationary per lane:
// lane l: o = l & 15, h = l >> 4 (n-half). Row tanh'd + staged in smem.
__global__ void __launch_bounds__(256, 1)
rnn_out_kernel(const float* __restrict__ states,  // [T*B, N]
               const float* __restrict__ Wout,    // [N, NOUT]
               const float* __restrict__ bout,    // [NOUT]
               float* __restrict__ outputs)       // [T*B, NOUT]
{
    __shared__ __align__(16) float srow[8][N_HID];

    const int tid  = threadIdx.x;
    const int wid  = tid >> 5;
    const int lane = tid & 31;
    const int o    = lane & 15;
    const int h    = lane >> 4;

    // packed Wout slice: w[j] = (Wout[h*128+2j][o], Wout[h*128+2j+1][o])
    ull w[64];
#pragma unroll
    for (int j = 0; j < 64; ++j) {
        int n = h * 128 + 2 * j;
        w[j] = pack2(Wout[n * N_OUT + o], Wout[(n + 1) * N_OUT + o]);
    }
    const float bo = bout[o];

    const int rows = T_STEPS * B_SZ;
    const int warps_total = (gridDim.x * blockDim.x) >> 5;
    for (int row = (blockIdx.x * blockDim.x + tid) >> 5; row < rows; row += warps_total) {
        const float4* src = reinterpret_cast<const float4*>(states + (size_t)row * N_HID);
        float4 v0 = src[lane];
        float4 v1 = src[32 + lane];
        v0.x = ftanh(v0.x); v0.y = ftanh(v0.y); v0.z = ftanh(v0.z); v0.w = ftanh(v0.w);
        v1.x = ftanh(v1.x); v1.y = ftanh(v1.y); v1.z = ftanh(v1.z); v1.w = ftanh(v1.w);
        float4* dst = reinterpret_cast<float4*>(&srow[wid][0]);
        dst[lane]      = v0;
        dst[32 + lane] = v1;
        __syncwarp();

        const ulonglong2* rp = reinterpret_cast<const ulonglong2*>(&srow[wid][h << 7]);
        ull a0 = 0, a1 = 0;
#pragma unroll
        for (int g = 0; g < 32; ++g) {
            ulonglong2 q = rp[g];
            ffma2(a0, w[2 * g + 0], q.x);
            ffma2(a1, w[2 * g + 1], q.y);
        }
        float zz = hadd2(fadd2(a0, a1));
        zz += __shfl_xor_sync(0xffffffffu, zz, 16);   // combine n-halves
        if (h == 0)
            outputs[(size_t)row * N_OUT + o] = zz + bo;
        __syncwarp();
    }
}

extern "C" void kernel_launch(void* const* d_in, const int* in_sizes, int n_in,
                              void* d_out, int out_size) {
    const float* inputs = (const float*)d_in[0];
    const float* noise  = (const float*)d_in[1];
    const float* x0     = (const float*)d_in[2];
    const float* Win    = (const float*)d_in[3];
    const float* Wrec   = (const float*)d_in[4];
    const float* brec   = (const float*)d_in[5];
    const float* Wout   = (const float*)d_in[6];
    const float* bout   = (const float*)d_in[7];

    float* outputs = (float*)d_out;                                  // [T,B,NOUT]
    float* states  = (float*)d_out + (size_t)T_STEPS * B_SZ * N_OUT; // [T,B,N]

    rnn_step_kernel<<<dim3(B_SZ), dim3(256)>>>(
        inputs, noise, x0, Win, Wrec, brec, states);
    rnn_out_kernel<<<dim3(296), dim3(256)>>>(states, Wout, bout, outputs);
}

// round 5
// speedup vs baseline: 1.7652x; 1.7652x over previous
#include <cuda_runtime.h>
#include <cstdint>

// Leaky RNN: x_t = 0.9*x_{t-1} + 0.1*(u@Win + tanh(x_{t-1})@Wrec + brec) + q_t
//            z_t = tanh(x_t)@Wout + bout
// T=1024, B=64, NIN=32, N=256, NOUT=16.
//
// Pre : g[t,b,n] = noise[t,b,n] + 0.1*(u[t,b,:]@Win[:,n] + brec[n])   (scratch)
// A   : 64 CTAs (1/batch), 256 thr, thread owns column gn. Wrec[:,gn] split:
//       k in [0,212) packed f32x2 register-stationary (212 regs, NO SPILL),
//       k in [212,256) in smem (lane-consecutive, conflict-free).
//       Step: r broadcast LDS -> 106 FFMA2 + 44 FFMA -> x update -> tanh -> STS.
// B   : outputs = tanh(states) @ Wout + bout, warp/row, prefetch-pipelined.

#define T_STEPS 1024
#define B_SZ    64
#define N_IN    32
#define N_HID   256
#define N_OUT   16
#define K_REG   212           // 106 packed pairs in registers
#define K_SM    44            // remainder from shared memory

typedef unsigned long long ull;

__device__ float g_buf[T_STEPS * B_SZ * N_HID];   // 64MB scratch (allowed)

__device__ __forceinline__ void ffma2(ull& acc, ull a, ull b) {
    asm("fma.rn.f32x2 %0, %1, %2, %0;" : "+l"(acc) : "l"(a), "l"(b));
}
__device__ __forceinline__ ull fadd2(ull a, ull b) {
    ull r; asm("add.rn.f32x2 %0, %1, %2;" : "=l"(r) : "l"(a), "l"(b)); return r;
}
__device__ __forceinline__ ull pack2(float lo, float hi) {
    ull r; asm("mov.b64 %0, {%1, %2};" : "=l"(r) : "f"(lo), "f"(hi)); return r;
}
__device__ __forceinline__ float hadd2(ull a) {
    float lo, hi; asm("mov.b64 {%0, %1}, %2;" : "=f"(lo), "=f"(hi) : "l"(a));
    return lo + hi;
}
__device__ __forceinline__ float ftanh(float x) {
    float e = __expf(2.0f * x);
    return 1.0f - __fdividef(2.0f, e + 1.0f);
}

// ---------------- Pre-kernel: g = noise + 0.1*(u@Win + brec) ----------------
__global__ void __launch_bounds__(256, 1)
uproj_kernel(const float* __restrict__ inputs,   // [T*B, NIN]
             const float* __restrict__ noise,    // [T*B, N]
             const float* __restrict__ Win,      // [NIN, N]
             const float* __restrict__ brec)     // [N]
{
    __shared__ float su[8][N_IN];
    const int tid = threadIdx.x;

    float w_in[N_IN];
#pragma unroll
    for (int i = 0; i < N_IN; ++i) w_in[i] = Win[i * N_HID + tid];
    const float br = brec[tid];

    const int row0 = blockIdx.x * 8;
    su[tid >> 5][tid & 31] = inputs[row0 * N_IN + tid];   // 8 rows x 32 = 256 vals
    __syncthreads();

#pragma unroll
    for (int rr = 0; rr < 8; ++rr) {
        const int row = row0 + rr;
        float acc = br;
#pragma unroll
        for (int i = 0; i < N_IN; ++i) acc = fmaf(su[rr][i], w_in[i], acc);
        g_buf[row * N_HID + tid] = noise[row * N_HID + tid] + 0.1f * acc;
    }
}

// ---------------- Kernel A: the recurrence ----------------
__global__ void __launch_bounds__(256, 1)
rnn_step_kernel(const float* __restrict__ x0,     // [B,N]
                const float* __restrict__ Wrec,   // [N,N]
                float* __restrict__ states)       // [T,B,N]
{
    __shared__ __align__(16) float r_s[2][N_HID];   // r double-buffered
    __shared__ float wsm[K_SM][N_HID];              // Wrec rows [212,256)

    const int tid = threadIdx.x;
    const int b   = blockIdx.x;
    const int gn  = tid;

    // register-stationary packed weights: w[j] = (Wrec[2j][gn], Wrec[2j+1][gn])
    ull w[K_REG / 2];                                // 106 ull = 212 regs
#pragma unroll
    for (int j = 0; j < K_REG / 2; ++j)
        w[j] = pack2(Wrec[(2 * j) * N_HID + gn], Wrec[(2 * j + 1) * N_HID + gn]);

    // smem-resident tail rows
    for (int i = 0; i < K_SM; ++i)
        wsm[i][gn] = Wrec[(K_REG + i) * N_HID + gn];

    float x = x0[b * N_HID + gn];
    r_s[0][gn] = ftanh(x);

    const float* gp = g_buf + b * N_HID + gn;
    float greg = gp[0];
    float* sp = states + b * N_HID + gn;
    __syncthreads();

#pragma unroll 1
    for (int t = 0; t < T_STEPS; ++t) {
        const int p  = t & 1;
        const int nb = p ^ 1;

        const int tq = (t + 1 < T_STEPS) ? (t + 1) : (T_STEPS - 1);
        const float gnext = gp[tq * (B_SZ * N_HID)];   // prefetch, hidden under dot

        // ---- register part: k in [0,212), 106 FFMA2, r broadcast LDS.128 ----
        const ulonglong2* rp = reinterpret_cast<const ulonglong2*>(&r_s[p][0]);
        ull a0 = 0, a1 = 0, a2 = 0, a3 = 0;
#pragma unroll
        for (int gq = 0; gq < 26; ++gq) {
            ulonglong2 q0 = rp[2 * gq];
            ulonglong2 q1 = rp[2 * gq + 1];
            ffma2(a0, w[4 * gq + 0], q0.x);
            ffma2(a1, w[4 * gq + 1], q0.y);
            ffma2(a2, w[4 * gq + 2], q1.x);
            ffma2(a3, w[4 * gq + 3], q1.y);
        }
        {   // tail pair: w[104], w[105] (k = 208..211)
            ulonglong2 q0 = rp[52];
            ffma2(a0, w[104], q0.x);
            ffma2(a1, w[105], q0.y);
        }

        // ---- smem part: k in [212,256), 44 FFMA, weights lane-consecutive ----
        const float4* rt4 = reinterpret_cast<const float4*>(&r_s[p][K_REG]);
        float s0 = 0.f, s1 = 0.f, s2 = 0.f, s3 = 0.f;
#pragma unroll
        for (int i = 0; i < K_SM / 4; ++i) {
            float4 v = rt4[i];
            s0 = fmaf(wsm[4 * i + 0][gn], v.x, s0);
            s1 = fmaf(wsm[4 * i + 1][gn], v.y, s1);
            s2 = fmaf(wsm[4 * i + 2][gn], v.z, s2);
            s3 = fmaf(wsm[4 * i + 3][gn], v.w, s3);
        }

        const float tot = hadd2(fadd2(fadd2(a0, a1), fadd2(a2, a3)))
                        + ((s0 + s1) + (s2 + s3));
        x = 0.9f * x + 0.1f * tot + greg;
        greg = gnext;

        sp[t * (B_SZ * N_HID)] = x;      // fire-and-forget STG
        r_s[nb][gn] = ftanh(x);

        __syncthreads();                 // r_s[nb] ready for t+1
    }
}

// ---------------- Kernel B: z = tanh(states) @ Wout + bout ----------------
__global__ void __launch_bounds__(256, 1)
rnn_out_kernel(const float* __restrict__ states,  // [T*B, N]
               const float* __restrict__ Wout,    // [N, NOUT]
               const float* __restrict__ bout,    // [NOUT]
               float* __restrict__ outputs)       // [T*B, NOUT]
{
    __shared__ __align__(16) float srow[8][N_HID];

    const int tid  = threadIdx.x;
    const int wid  = tid >> 5;
    const int lane = tid & 31;
    const int o    = lane & 15;
    const int h    = lane >> 4;

    ull w[64];                           // (Wout[h*128+2j][o], Wout[h*128+2j+1][o])
#pragma unroll
    for (int j = 0; j < 64; ++j) {
        int n = h * 128 + 2 * j;
        w[j] = pack2(Wout[n * N_OUT + o], Wout[(n + 1) * N_OUT + o]);
    }
    const float bo = bout[o];

    const int rows = T_STEPS * B_SZ;
    const int warps_total = (gridDim.x * blockDim.x) >> 5;
    int row = (blockIdx.x * blockDim.x + tid) >> 5;

    if (row >= rows) return;
    // software pipeline: keep next row's loads in flight during current dot
    const float4* src = reinterpret_cast<const float4*>(states + (size_t)row * N_HID);
    float4 v0 = src[lane];
    float4 v1 = src[32 + lane];

    while (true) {
        const int nrow = row + warps_total;
        float4 n0, n1;
        if (nrow < rows) {
            const float4* nsrc = reinterpret_cast<const float4*>(states + (size_t)nrow * N_HID);
            n0 = nsrc[lane];
            n1 = nsrc[32 + lane];
        }

        v0.x = ftanh(v0.x); v0.y = ftanh(v0.y); v0.z = ftanh(v0.z); v0.w = ftanh(v0.w);
        v1.x = ftanh(v1.x); v1.y = ftanh(v1.y); v1.z = ftanh(v1.z); v1.w = ftanh(v1.w);
        float4* dst = reinterpret_cast<float4*>(&srow[wid][0]);
        dst[lane]      = v0;
        dst[32 + lane] = v1;
        __syncwarp();

        const ulonglong2* rp = reinterpret_cast<const ulonglong2*>(&srow[wid][h << 7]);
        ull a0 = 0, a1 = 0;
#pragma unroll
        for (int gq = 0; gq < 32; ++gq) {
            ulonglong2 q = rp[gq];
            ffma2(a0, w[2 * gq + 0], q.x);
            ffma2(a1, w[2 * gq + 1], q.y);
        }
        float zz = hadd2(fadd2(a0, a1));
        zz += __shfl_xor_sync(0xffffffffu, zz, 16);
        if (h == 0)
            outputs[(size_t)row * N_OUT + o] = zz + bo;
        __syncwarp();

        if (nrow >= rows) break;
        row = nrow; v0 = n0; v1 = n1;
    }
}

extern "C" void kernel_launch(void* const* d_in, const int* in_sizes, int n_in,
                              void* d_out, int out_size) {
    const float* inputs = (const float*)d_in[0];
    const float* noise  = (const float*)d_in[1];
    const float* x0     = (const float*)d_in[2];
    const float* Win    = (const float*)d_in[3];
    const float* Wrec   = (const float*)d_in[4];
    const float* brec   = (const float*)d_in[5];
    const float* Wout   = (const float*)d_in[6];
    const float* bout   = (const float*)d_in[7];

    float* outputs = (float*)d_out;                                  // [T,B,NOUT]
    float* states  = (float*)d_out + (size_t)T_STEPS * B_SZ * N_OUT; // [T,B,N]

    uproj_kernel<<<dim3(T_STEPS * B_SZ / 8), dim3(256)>>>(inputs, noise, Win, brec);
    rnn_step_kernel<<<dim3(B_SZ), dim3(256)>>>(x0, Wrec, states);
    rnn_out_kernel<<<dim3(592), dim3(256)>>>(states, Wout, bout, outputs);
}